// round 1
// baseline (speedup 1.0000x reference)
#include <cuda_runtime.h>
#include <stdint.h>

#define BATCH 16
#define NNODE 16384
#define DIM   128
#define NEDGE 65536

// -------------------- device scratch (no allocs allowed) --------------------
__device__ int    g_is64;                 // 1 if edge_index is int64
__device__ int    g_edge[2 * NEDGE];      // converted int32 edges [src | dst]
__device__ int    g_deg[NNODE];
__device__ int    g_rowstart[NNODE + 1];
__device__ int    g_cursor[NNODE];
__device__ int    g_csr[NEDGE];
__device__ float4 g_neigh[(size_t)BATCH * NNODE * (DIM / 4)];  // 134 MB

// -------------------- edge dtype detection + conversion --------------------
// If int64: odd int32 words (high halves) of the first 32 entries are all 0
// (values in [0, 16384)). If int32: they are real edge ids, ~never all zero.
__global__ void k_detect(const int* e32) {
    int lane = threadIdx.x;                 // 32 threads
    int v = e32[2 * lane + 1];
    unsigned mask = __ballot_sync(0xFFFFFFFFu, v == 0);
    if (lane == 0) g_is64 = (mask == 0xFFFFFFFFu) ? 1 : 0;
}

__global__ void k_convert(const void* ei) {
    int i = blockIdx.x * blockDim.x + threadIdx.x;
    if (i < 2 * NEDGE) {
        if (g_is64) g_edge[i] = (int)((const long long*)ei)[i];
        else        g_edge[i] = ((const int*)ei)[i];
    }
}

// -------------------- CSR build --------------------
__global__ void k_zero_deg() {
    int i = blockIdx.x * blockDim.x + threadIdx.x;
    if (i < NNODE) g_deg[i] = 0;
}

__global__ void k_count() {
    int e = blockIdx.x * blockDim.x + threadIdx.x;
    if (e < NEDGE) atomicAdd(&g_deg[g_edge[NEDGE + e]], 1);
}

// single-block exclusive scan of 16384 degrees (1024 thr x 16)
__global__ void k_scan() {
    __shared__ int sums[1024];
    int t = threadIdx.x;
    int loc[16];
    int s = 0;
#pragma unroll
    for (int i = 0; i < 16; i++) { loc[i] = s; s += g_deg[t * 16 + i]; }
    sums[t] = s;
    __syncthreads();
    for (int off = 1; off < 1024; off <<= 1) {
        int v = (t >= off) ? sums[t - off] : 0;
        __syncthreads();
        sums[t] += v;
        __syncthreads();
    }
    int base = (t == 0) ? 0 : sums[t - 1];
#pragma unroll
    for (int i = 0; i < 16; i++) {
        int r = base + loc[i];
        g_rowstart[t * 16 + i] = r;
        g_cursor[t * 16 + i] = r;
    }
    if (t == 1023) g_rowstart[NNODE] = sums[1023];
}

__global__ void k_fill() {
    int e = blockIdx.x * blockDim.x + threadIdx.x;
    if (e < NEDGE) {
        int d = g_edge[NEDGE + e];
        int p = atomicAdd(&g_cursor[d], 1);
        g_csr[p] = g_edge[e];
    }
}

// sort each node's (tiny, avg 4) neighbor list -> deterministic fp32 sum order
__global__ void k_sort() {
    int n = blockIdx.x * blockDim.x + threadIdx.x;
    if (n < NNODE) {
        int s = g_rowstart[n], e = g_rowstart[n + 1];
        for (int i = s + 1; i < e; i++) {
            int v = g_csr[i];
            int j = i - 1;
            while (j >= s && g_csr[j] > v) { g_csr[j + 1] = g_csr[j]; j--; }
            g_csr[j + 1] = v;
        }
    }
}

// -------------------- neighbor mean aggregation --------------------
// one warp per (node, batch); lane handles 4 features (float4)
__global__ void __launch_bounds__(256) k_agg(const float* __restrict__ x) {
    int warp = threadIdx.x >> 5, lane = threadIdx.x & 31;
    int n = blockIdx.x * 8 + warp;
    int b = blockIdx.y;
    int s = g_rowstart[n], e = g_rowstart[n + 1];
    const float4* xb = (const float4*)(x) + (size_t)b * NNODE * (DIM / 4);
    float4 acc = make_float4(0.f, 0.f, 0.f, 0.f);
    for (int i = s; i < e; i++) {
        int src = g_csr[i];
        float4 v = xb[(size_t)src * 32 + lane];
        acc.x += v.x; acc.y += v.y; acc.z += v.z; acc.w += v.w;
    }
    float inv = 1.0f / fmaxf((float)(e - s), 1.0f);
    acc.x *= inv; acc.y *= inv; acc.z *= inv; acc.w *= inv;
    g_neigh[((size_t)b * NNODE + n) * 32 + lane] = acc;
}

// -------------------- fused GEMM (K=256 concat) + bias + LayerNorm + ReLU ---
// out[r, :] = LN( x[r]·Ws^T + neigh[r]·Wn^T + bias ) then ReLU
// BM=64 rows/CTA, BN=128 (full D_OUT -> LN intra-CTA), BK=16, 256 threads,
// thread tile 4x8.
#define BM  64
#define LDA 65
#define LDB 129
#define LDO 132

__global__ void __launch_bounds__(256) k_gemm_ln(
    const float* __restrict__ x, const float* __restrict__ Ws,
    const float* __restrict__ Wn, const float* __restrict__ bias,
    const float* __restrict__ gamma, const float* __restrict__ beta,
    float* __restrict__ out)
{
    __shared__ float smem[BM * LDO];          // 8448 floats = 33 KB
    float* As = smem;                          // 16*65  = 1040
    float* Bs = smem + 1040;                   // 16*129 = 2064

    int tid = threadIdx.x;
    int tx = tid & 15, ty = tid >> 4;
    int row0 = blockIdx.x * BM;
    const float* neigh = (const float*)g_neigh;

    float acc[4][8];
#pragma unroll
    for (int i = 0; i < 4; i++)
#pragma unroll
        for (int j = 0; j < 8; j++) acc[i][j] = 0.f;

    for (int kk = 0; kk < 16; kk++) {
        // A tile: 64 rows x 16 k; thread t loads float4 at (m=t/4, k=(t%4)*4)
        {
            int m = tid >> 2, k = (tid & 3) * 4;
            int kg = kk * 16 + k;
            const float* p = (kg < 128)
                ? (x + (size_t)(row0 + m) * 128 + kg)
                : (neigh + (size_t)(row0 + m) * 128 + (kg - 128));
            float4 v = *(const float4*)p;
            As[(k + 0) * LDA + m] = v.x;
            As[(k + 1) * LDA + m] = v.y;
            As[(k + 2) * LDA + m] = v.z;
            As[(k + 3) * LDA + m] = v.w;
        }
        // B tile: 128 cols x 16 k; thread t: j=t/2, k0=(t%2)*8, two float4
        {
            int j = tid >> 1, k0 = (tid & 1) * 8;
            int kg = kk * 16 + k0;
            const float* wp = (kg < 128) ? (Ws + j * 128 + kg)
                                         : (Wn + j * 128 + (kg - 128));
            float4 v0 = *(const float4*)wp;
            float4 v1 = *(const float4*)(wp + 4);
            Bs[(k0 + 0) * LDB + j] = v0.x;
            Bs[(k0 + 1) * LDB + j] = v0.y;
            Bs[(k0 + 2) * LDB + j] = v0.z;
            Bs[(k0 + 3) * LDB + j] = v0.w;
            Bs[(k0 + 4) * LDB + j] = v1.x;
            Bs[(k0 + 5) * LDB + j] = v1.y;
            Bs[(k0 + 6) * LDB + j] = v1.z;
            Bs[(k0 + 7) * LDB + j] = v1.w;
        }
        __syncthreads();
#pragma unroll
        for (int k = 0; k < 16; k++) {
            float a[4], b[8];
#pragma unroll
            for (int i = 0; i < 4; i++) a[i] = As[k * LDA + ty * 4 + i];
#pragma unroll
            for (int j = 0; j < 8; j++) b[j] = Bs[k * LDB + tx * 8 + j];
#pragma unroll
            for (int i = 0; i < 4; i++)
#pragma unroll
                for (int j = 0; j < 8; j++) acc[i][j] += a[i] * b[j];
        }
        __syncthreads();
    }

    // stage result (+bias) to smem for row-wise LN
#pragma unroll
    for (int i = 0; i < 4; i++)
#pragma unroll
        for (int j = 0; j < 8; j++)
            smem[(ty * 4 + i) * LDO + tx * 8 + j] = acc[i][j] + bias[tx * 8 + j];
    __syncthreads();

    // LN + ReLU: 8 warps x 8 rows; lane handles 4 cols
    int warp = tid >> 5, lane = tid & 31;
#pragma unroll
    for (int r8 = 0; r8 < 8; r8++) {
        int r = warp * 8 + r8;
        int c = lane * 4;
        float v0 = smem[r * LDO + c + 0];
        float v1 = smem[r * LDO + c + 1];
        float v2 = smem[r * LDO + c + 2];
        float v3 = smem[r * LDO + c + 3];
        float s  = v0 + v1 + v2 + v3;
        float sq = v0 * v0 + v1 * v1 + v2 * v2 + v3 * v3;
#pragma unroll
        for (int off = 16; off >= 1; off >>= 1) {
            s  += __shfl_xor_sync(0xFFFFFFFFu, s,  off);
            sq += __shfl_xor_sync(0xFFFFFFFFu, sq, off);
        }
        float mean = s * (1.0f / 128.0f);
        float var  = sq * (1.0f / 128.0f) - mean * mean;
        float rstd = rsqrtf(var + 1e-5f);
        float4 o;
        o.x = fmaxf((v0 - mean) * rstd * gamma[c + 0] + beta[c + 0], 0.f);
        o.y = fmaxf((v1 - mean) * rstd * gamma[c + 1] + beta[c + 1], 0.f);
        o.z = fmaxf((v2 - mean) * rstd * gamma[c + 2] + beta[c + 2], 0.f);
        o.w = fmaxf((v3 - mean) * rstd * gamma[c + 3] + beta[c + 3], 0.f);
        *(float4*)(out + (size_t)(row0 + r) * 128 + c) = o;
    }
}

// -------------------- launch --------------------
extern "C" void kernel_launch(void* const* d_in, const int* in_sizes, int n_in,
                              void* d_out, int out_size) {
    const float* x  = (const float*)d_in[0];
    const void*  ei = d_in[1];
    // batch_size scalar may or may not be materialized as an input
    int o = (n_in >= 8) ? 3 : 2;
    const float* Ws    = (const float*)d_in[o + 0];
    const float* Wn    = (const float*)d_in[o + 1];
    const float* bias  = (const float*)d_in[o + 2];
    const float* gamma = (const float*)d_in[o + 3];
    const float* beta  = (const float*)d_in[o + 4];
    float* out = (float*)d_out;

    k_detect<<<1, 32>>>((const int*)ei);
    k_convert<<<(2 * NEDGE + 255) / 256, 256>>>(ei);
    k_zero_deg<<<NNODE / 256, 256>>>();
    k_count<<<NEDGE / 256, 256>>>();
    k_scan<<<1, 1024>>>();
    k_fill<<<NEDGE / 256, 256>>>();
    k_sort<<<NNODE / 256, 256>>>();

    dim3 ga(NNODE / 8, BATCH);
    k_agg<<<ga, 256>>>(x);

    k_gemm_ln<<<(BATCH * NNODE) / BM, 256>>>(x, Ws, Wn, bias, gamma, beta, out);
}

// round 7
// speedup vs baseline: 1.8839x; 1.8839x over previous
#include <cuda_runtime.h>
#include <cuda_bf16.h>
#include <stdint.h>

#define BATCH 16
#define NNODE 16384
#define DIM   128
#define NEDGE 65536
#define NROWS (BATCH * NNODE)

// -------------------- device scratch (no allocs allowed) --------------------
__device__ int    g_is64;
__device__ int    g_edge[2 * NEDGE];
__device__ int    g_deg[NNODE];
__device__ int    g_rowstart[NNODE + 1];
__device__ int    g_cursor[NNODE];
__device__ int    g_csr[NEDGE];
__device__ float4 g_neigh[(size_t)NROWS * (DIM / 4)];   // 134 MB fp32
__device__ __nv_bfloat16 g_Wsh[DIM * DIM];
__device__ __nv_bfloat16 g_Wsl[DIM * DIM];
__device__ __nv_bfloat16 g_Wnh[DIM * DIM];
__device__ __nv_bfloat16 g_Wnl[DIM * DIM];

// ==================== helpers ====================
__device__ __forceinline__ uint32_t smem_u32(const void* p) {
    uint32_t a;
    asm("{ .reg .u64 t; cvta.to.shared.u64 t, %1; cvt.u32.u64 %0, t; }"
        : "=r"(a) : "l"(p));
    return a;
}
__device__ __forceinline__ uint32_t pk2(__nv_bfloat16 a, __nv_bfloat16 b) {
    return (uint32_t)__bfloat16_as_ushort(a) | ((uint32_t)__bfloat16_as_ushort(b) << 16);
}

#define LDM_X4(r0, r1, r2, r3, addr) \
    asm volatile("ldmatrix.sync.aligned.m8n8.x4.shared.b16 {%0,%1,%2,%3}, [%4];" \
                 : "=r"(r0), "=r"(r1), "=r"(r2), "=r"(r3) : "r"(addr))

#define MMA16816(c, a, b0, b1) \
    asm volatile("mma.sync.aligned.m16n8k16.row.col.f32.bf16.bf16.f32 " \
                 "{%0,%1,%2,%3}, {%4,%5,%6,%7}, {%8,%9}, {%0,%1,%2,%3};" \
                 : "+f"((c)[0]), "+f"((c)[1]), "+f"((c)[2]), "+f"((c)[3]) \
                 : "r"((a)[0]), "r"((a)[1]), "r"((a)[2]), "r"((a)[3]), \
                   "r"(b0), "r"(b1))

// ==================== preprocessing kernels ====================
__global__ void k_detect(const int* e32) {
    int lane = threadIdx.x;
    int v = e32[2 * lane + 1];
    unsigned mask = __ballot_sync(0xFFFFFFFFu, v == 0);
    if (lane == 0) g_is64 = (mask == 0xFFFFFFFFu) ? 1 : 0;
}
__global__ void k_convert(const void* ei) {
    int i = blockIdx.x * blockDim.x + threadIdx.x;
    if (i < 2 * NEDGE) {
        if (g_is64) g_edge[i] = (int)((const long long*)ei)[i];
        else        g_edge[i] = ((const int*)ei)[i];
    }
}
__global__ void k_zero_deg() {
    int i = blockIdx.x * blockDim.x + threadIdx.x;
    if (i < NNODE) g_deg[i] = 0;
}
__global__ void k_count() {
    int e = blockIdx.x * blockDim.x + threadIdx.x;
    if (e < NEDGE) atomicAdd(&g_deg[g_edge[NEDGE + e]], 1);
}
__global__ void k_scan() {
    __shared__ int sums[1024];
    int t = threadIdx.x;
    int loc[16];
    int s = 0;
#pragma unroll
    for (int i = 0; i < 16; i++) { loc[i] = s; s += g_deg[t * 16 + i]; }
    sums[t] = s;
    __syncthreads();
    for (int off = 1; off < 1024; off <<= 1) {
        int v = (t >= off) ? sums[t - off] : 0;
        __syncthreads();
        sums[t] += v;
        __syncthreads();
    }
    int base = (t == 0) ? 0 : sums[t - 1];
#pragma unroll
    for (int i = 0; i < 16; i++) {
        int r = base + loc[i];
        g_rowstart[t * 16 + i] = r;
        g_cursor[t * 16 + i] = r;
    }
    if (t == 1023) g_rowstart[NNODE] = sums[1023];
}
__global__ void k_fill() {
    int e = blockIdx.x * blockDim.x + threadIdx.x;
    if (e < NEDGE) {
        int d = g_edge[NEDGE + e];
        int p = atomicAdd(&g_cursor[d], 1);
        g_csr[p] = g_edge[e];
    }
}
__global__ void k_sort() {
    int n = blockIdx.x * blockDim.x + threadIdx.x;
    if (n < NNODE) {
        int s = g_rowstart[n], e = g_rowstart[n + 1];
        for (int i = s + 1; i < e; i++) {
            int v = g_csr[i];
            int j = i - 1;
            while (j >= s && g_csr[j] > v) { g_csr[j + 1] = g_csr[j]; j--; }
            g_csr[j + 1] = v;
        }
    }
}
__global__ void k_convw(const float* Ws, const float* Wn) {
    int i = blockIdx.x * blockDim.x + threadIdx.x;
    if (i < DIM * DIM) {
        float a = Ws[i];
        __nv_bfloat16 h = __float2bfloat16_rn(a);
        g_Wsh[i] = h;
        g_Wsl[i] = __float2bfloat16_rn(a - __bfloat162float(h));
        float b = Wn[i];
        __nv_bfloat16 h2 = __float2bfloat16_rn(b);
        g_Wnh[i] = h2;
        g_Wnl[i] = __float2bfloat16_rn(b - __bfloat162float(h2));
    }
}

// -------------------- neighbor mean aggregation --------------------
__global__ void __launch_bounds__(256) k_agg(const float* __restrict__ x) {
    int warp = threadIdx.x >> 5, lane = threadIdx.x & 31;
    int n = blockIdx.x * 8 + warp;
    int b = blockIdx.y;
    int s = g_rowstart[n], e = g_rowstart[n + 1];
    const float4* xb = (const float4*)(x) + (size_t)b * NNODE * (DIM / 4);
    float4 acc = make_float4(0.f, 0.f, 0.f, 0.f);
    for (int i = s; i < e; i++) {
        int src = g_csr[i];
        float4 v = xb[(size_t)src * 32 + lane];
        acc.x += v.x; acc.y += v.y; acc.z += v.z; acc.w += v.w;
    }
    float inv = 1.0f / fmaxf((float)(e - s), 1.0f);
    acc.x *= inv; acc.y *= inv; acc.z *= inv; acc.w *= inv;
    g_neigh[((size_t)b * NNODE + n) * 32 + lane] = acc;
}

// ==================== HMMA (mma.sync) GEMM + bias + LN + ReLU ====================
// CTA: 128 rows x 128 cols, 256 threads = 8 warps in 4(m) x 2(n) grid.
// Warp tile: m32 x n64 = 2 x 8 m16n8k16 atoms. K_physical = 256 (x | neigh),
// processed as 4 phases of 64 fp32 cols, split in-kernel to hi/lo bf16.
// 3 terms per k16 step: (Ah,Bh), (Al,Bh), (Ah,Bl).
// smem tiles (row stride 144 B, conflict-free for ldmatrix):
//   sAh @0, sAl @18432, sBh @36864, sBl @55296  (total 73728 B)
// Epilogue stage (128 x 132 f32 = 67584 B) aliases the tiles.
#define RS    144
#define SA_H  0u
#define SA_L  18432u
#define SB_H  36864u
#define SB_L  55296u
#define GEMM_SMEM 73728

__global__ void __launch_bounds__(256, 2) k_gemm_ln(
    const float* __restrict__ x, const float* __restrict__ bias,
    const float* __restrict__ gamma, const float* __restrict__ beta,
    float* __restrict__ out)
{
    extern __shared__ char dsm[];
    uint32_t sbase = smem_u32(dsm);
    int tid = threadIdx.x;
    int lane = tid & 31, wid = tid >> 5;
    int wm = wid & 3, wn = wid >> 2;          // 4 m-slices x 2 n-slices
    int row0 = blockIdx.x * 128;
    const float* nb = (const float*)g_neigh;

    const float* asrc[4] = { x + (size_t)row0 * 128, x + (size_t)row0 * 128 + 64,
                             nb + (size_t)row0 * 128, nb + (size_t)row0 * 128 + 64 };
    const __nv_bfloat16* b0src[4] = { g_Wsh, g_Wsh + 64, g_Wnh, g_Wnh + 64 };
    const __nv_bfloat16* b1src[4] = { g_Wsl, g_Wsl + 64, g_Wnl, g_Wnl + 64 };

    float acc[2][8][4];
#pragma unroll
    for (int mt = 0; mt < 2; mt++)
#pragma unroll
        for (int nt = 0; nt < 8; nt++)
#pragma unroll
            for (int j = 0; j < 4; j++) acc[mt][nt][j] = 0.f;

    // ldmatrix lane addressing (x4 tile order matches fragment reg order)
    uint32_t aRow = (uint32_t)(wm * 32 + (lane & 15));
    uint32_t aK   = (uint32_t)((lane >> 4) << 4);                    // +16B for k8 half
    uint32_t bRow = (uint32_t)(wn * 64 + (lane & 7) + ((lane >> 4) << 3));
    uint32_t bK   = (uint32_t)(((lane >> 3) & 1) << 4);

    for (int p = 0; p < 4; p++) {
        if (p) __syncthreads();   // previous phase's reads done before refill

        // ---- fill A: 128 rows x 64 fp32 -> hi/lo bf16 tiles ----
        {
            const float4* ap = (const float4*)asrc[p];
#pragma unroll
            for (int i = 0; i < 8; i++) {
                int u = tid + 256 * i;            // 2048 float4 units
                int r = u >> 4, c4 = u & 15;
                float4 v = ap[r * 32 + c4];
                __nv_bfloat16 h0 = __float2bfloat16_rn(v.x);
                __nv_bfloat16 h1 = __float2bfloat16_rn(v.y);
                __nv_bfloat16 h2 = __float2bfloat16_rn(v.z);
                __nv_bfloat16 h3 = __float2bfloat16_rn(v.w);
                uint2 hi = make_uint2(pk2(h0, h1), pk2(h2, h3));
                uint2 lo = make_uint2(
                    pk2(__float2bfloat16_rn(v.x - __bfloat162float(h0)),
                        __float2bfloat16_rn(v.y - __bfloat162float(h1))),
                    pk2(__float2bfloat16_rn(v.z - __bfloat162float(h2)),
                        __float2bfloat16_rn(v.w - __bfloat162float(h3))));
                uint32_t off = (uint32_t)(r * RS + c4 * 8);
                *(uint2*)(dsm + SA_H + off) = hi;
                *(uint2*)(dsm + SA_L + off) = lo;
            }
        }
        // ---- fill B: 2 tiles of 128 n-rows x 64 k bf16 ----
        {
#pragma unroll
            for (int i = 0; i < 8; i++) {
                int u = tid + 256 * i;            // 2048 uint4 units
                int ch = u >> 10, r = (u >> 3) & 127, s = u & 7;
                const __nv_bfloat16* src = ch ? b1src[p] : b0src[p];
                uint4 v = *(const uint4*)(src + r * 128 + s * 8);
                uint32_t off = (uint32_t)(r * RS + s * 16);
                *(uint4*)(dsm + (ch ? SB_L : SB_H) + off) = v;
            }
        }
        __syncthreads();

        // ---- compute: 4 k16 steps x 3 terms ----
#pragma unroll
        for (int ks = 0; ks < 4; ks++) {
            uint32_t kb = (uint32_t)(ks * 32);     // 16 bf16 * 2B
            uint32_t ah[2][4], al[2][4];
#pragma unroll
            for (int mt = 0; mt < 2; mt++) {
                uint32_t ra = sbase + (aRow + mt * 16) * RS + kb + aK;
                LDM_X4(ah[mt][0], ah[mt][1], ah[mt][2], ah[mt][3], ra + SA_H);
                LDM_X4(al[mt][0], al[mt][1], al[mt][2], al[mt][3], ra + SA_L);
            }
#pragma unroll
            for (int j = 0; j < 4; j++) {          // j = n16 group (2 atoms)
                uint32_t rb = sbase + (bRow + j * 16) * RS + kb + bK;
                uint32_t bh[4], bl[4];
                LDM_X4(bh[0], bh[1], bh[2], bh[3], rb + SB_H);
                LDM_X4(bl[0], bl[1], bl[2], bl[3], rb + SB_L);
#pragma unroll
                for (int mt = 0; mt < 2; mt++) {
#pragma unroll
                    for (int q = 0; q < 2; q++) {  // atom within n16
                        int nt = j * 2 + q;
                        MMA16816(acc[mt][nt], ah[mt], bh[q * 2], bh[q * 2 + 1]);
                        MMA16816(acc[mt][nt], al[mt], bh[q * 2], bh[q * 2 + 1]);
                        MMA16816(acc[mt][nt], ah[mt], bl[q * 2], bl[q * 2 + 1]);
                    }
                }
            }
        }
    }
    __syncthreads();

    // ---- stage C + bias to smem (aliases tiles) ----
    float* stage = (float*)dsm;                    // [128][132]
    int g = lane >> 2, tig = lane & 3;
#pragma unroll
    for (int nt = 0; nt < 8; nt++) {
        int col = wn * 64 + nt * 8 + tig * 2;
        float b0 = __ldg(&bias[col]), b1 = __ldg(&bias[col + 1]);
#pragma unroll
        for (int mt = 0; mt < 2; mt++) {
            int r = wm * 32 + mt * 16 + g;
            *(float2*)&stage[r * 132 + col] =
                make_float2(acc[mt][nt][0] + b0, acc[mt][nt][1] + b1);
            *(float2*)&stage[(r + 8) * 132 + col] =
                make_float2(acc[mt][nt][2] + b0, acc[mt][nt][3] + b1);
        }
    }
    __syncthreads();

    // ---- LN + ReLU + write: 2 threads per row (64 cols each) ----
    {
        int row = tid >> 1, hf = tid & 1;
        const float* rp = &stage[row * 132 + hf * 64];
        float sum = 0.f, sq = 0.f;
#pragma unroll
        for (int c4 = 0; c4 < 16; c4++) {
            float4 v = *(const float4*)(rp + c4 * 4);
            sum += v.x + v.y + v.z + v.w;
            sq  += v.x * v.x + v.y * v.y + v.z * v.z + v.w * v.w;
        }
        sum += __shfl_xor_sync(0xFFFFFFFFu, sum, 1);
        sq  += __shfl_xor_sync(0xFFFFFFFFu, sq, 1);
        float mean = sum * (1.0f / 128.0f);
        float var  = sq * (1.0f / 128.0f) - mean * mean;
        float rstd = rsqrtf(var + 1e-5f);
        float* op = out + (size_t)(row0 + row) * 128 + hf * 64;
#pragma unroll
        for (int c4 = 0; c4 < 16; c4++) {
            float4 v = *(const float4*)(rp + c4 * 4);
            float4 gm = *(const float4*)(gamma + hf * 64 + c4 * 4);
            float4 bt = *(const float4*)(beta + hf * 64 + c4 * 4);
            float4 o;
            o.x = fmaxf((v.x - mean) * rstd * gm.x + bt.x, 0.f);
            o.y = fmaxf((v.y - mean) * rstd * gm.y + bt.y, 0.f);
            o.z = fmaxf((v.z - mean) * rstd * gm.z + bt.z, 0.f);
            o.w = fmaxf((v.w - mean) * rstd * gm.w + bt.w, 0.f);
            *(float4*)(op + c4 * 4) = o;
        }
    }
}

// -------------------- launch --------------------
extern "C" void kernel_launch(void* const* d_in, const int* in_sizes, int n_in,
                              void* d_out, int out_size) {
    const float* x  = (const float*)d_in[0];
    const void*  ei = d_in[1];
    int o = (n_in >= 8) ? 3 : 2;
    const float* Ws    = (const float*)d_in[o + 0];
    const float* Wn    = (const float*)d_in[o + 1];
    const float* bias  = (const float*)d_in[o + 2];
    const float* gamma = (const float*)d_in[o + 3];
    const float* beta  = (const float*)d_in[o + 4];
    float* out = (float*)d_out;

    k_detect<<<1, 32>>>((const int*)ei);
    k_convert<<<(2 * NEDGE + 255) / 256, 256>>>(ei);
    k_zero_deg<<<NNODE / 256, 256>>>();
    k_count<<<NEDGE / 256, 256>>>();
    k_scan<<<1, 1024>>>();
    k_fill<<<NEDGE / 256, 256>>>();
    k_sort<<<NNODE / 256, 256>>>();
    k_convw<<<(DIM * DIM + 255) / 256, 256>>>(Ws, Wn);

    dim3 ga(NNODE / 8, BATCH);
    k_agg<<<ga, 256>>>(x);

    cudaFuncSetAttribute(k_gemm_ln, cudaFuncAttributeMaxDynamicSharedMemorySize, GEMM_SMEM);
    k_gemm_ln<<<NROWS / 128, 256, GEMM_SMEM>>>(x, bias, gamma, beta, out);
}